// round 1
// baseline (speedup 1.0000x reference)
#include <cuda_runtime.h>
#include <cuda_bf16.h>
#include <cstdint>

#define LL 65536
#define DD 256
#define CC 512      // number of chunks
#define RR 128      // rows per chunk (LL / CC)
#define NSEG 8      // segments for the W chunk-prefix scan (CC / 64)

#define NEG_INF __int_as_float(0xff800000)

// ---- scratch (device globals; no allocation allowed) ----
__device__ float g_s[LL];            // s[i] = K[i]·q
__device__ float g_M[CC], g_U[CC];   // per-chunk aggregates (U referenced to M)
__device__ float g_W[CC * DD];       // per-chunk vector aggregate (ref M_c)
__device__ float g_Mp[CC], g_Up[CC]; // exclusive prefix (Up referenced to Mp)
__device__ float g_alpha[CC], g_gamma[CC];
__device__ float g_Wp[CC * DD];      // segment-local exclusive W prefix (ref Mp_c)
__device__ float g_seg[NSEG * DD];   // segment aggregates (ref Minc[seg end])
__device__ float g_carry[NSEG * DD]; // exclusive segment carry (ref Mp[64*seg])

// ============================================================
// Pass 1: s = K·q ; per-chunk (M, U, W) reduction
// ============================================================
__global__ __launch_bounds__(256) void k_pass1(const float* __restrict__ K,
                                               const float* __restrict__ V,
                                               const float* __restrict__ q) {
    __shared__ float q_sh[DD];
    __shared__ float s_sh[RR];
    __shared__ float e_sh[RR];
    __shared__ float red_sh[8];
    __shared__ float wpart[4][DD];
    __shared__ float Mbc;

    const int c = blockIdx.x;
    const int t = threadIdx.x;
    const int lane = t & 31;
    const int wid = t >> 5;

    q_sh[t] = q[t];
    __syncthreads();

    const float4* q4 = reinterpret_cast<const float4*>(q_sh);
    const float4* K4 = reinterpret_cast<const float4*>(K) + (size_t)c * RR * (DD / 4);

    // --- s for this chunk: 8 warps x 16 rows, one warp per row ---
    float4 qa = q4[lane], qb = q4[32 + lane];
    for (int k = 0; k < 16; k++) {
        int r = wid * 16 + k;
        float4 ka = K4[r * 64 + lane];
        float4 kb = K4[r * 64 + 32 + lane];
        float p = ka.x * qa.x + ka.y * qa.y + ka.z * qa.z + ka.w * qa.w
                + kb.x * qb.x + kb.y * qb.y + kb.z * qb.z + kb.w * qb.w;
#pragma unroll
        for (int o = 16; o; o >>= 1) p += __shfl_xor_sync(0xffffffffu, p, o);
        if (lane == 0) s_sh[r] = p;
    }
    __syncthreads();

    if (t < RR) g_s[c * RR + t] = s_sh[t];

    // --- chunk max M ---
    float m = (t < RR) ? s_sh[t] : NEG_INF;
#pragma unroll
    for (int o = 16; o; o >>= 1) m = fmaxf(m, __shfl_xor_sync(0xffffffffu, m, o));
    if (lane == 0) red_sh[wid] = m;
    __syncthreads();
    if (t == 0) {
        float mm = NEG_INF;
#pragma unroll
        for (int w = 0; w < 8; w++) mm = fmaxf(mm, red_sh[w]);
        Mbc = mm;
    }
    __syncthreads();
    const float M = Mbc;

    if (t < RR) e_sh[t] = __expf(s_sh[t] - M);
    __syncthreads();

    // --- U = sum e ---
    float uu = (t < RR) ? e_sh[t] : 0.f;
#pragma unroll
    for (int o = 16; o; o >>= 1) uu += __shfl_xor_sync(0xffffffffu, uu, o);
    __syncthreads();   // red_sh reuse
    if (lane == 0) red_sh[wid] = uu;
    __syncthreads();
    if (t == 0) {
        float U = 0.f;
#pragma unroll
        for (int w = 0; w < 8; w++) U += red_sh[w];
        g_M[c] = M;
        g_U[c] = U;
    }

    // --- W[d] = sum_i e_i * V[i][d] ; 4 row-groups x 64 float4-lanes ---
    const int grp = t >> 6;
    const int j = t & 63;
    const float4* V4 = reinterpret_cast<const float4*>(V) + (size_t)c * RR * 64;
    float4 acc = make_float4(0.f, 0.f, 0.f, 0.f);
#pragma unroll 8
    for (int i = grp; i < RR; i += 4) {
        float e = e_sh[i];
        float4 v = V4[i * 64 + j];
        acc.x += e * v.x; acc.y += e * v.y; acc.z += e * v.z; acc.w += e * v.w;
    }
    reinterpret_cast<float4*>(wpart[grp])[j] = acc;
    __syncthreads();
    float W = wpart[0][t] + wpart[1][t] + wpart[2][t] + wpart[3][t];
    g_W[(size_t)c * DD + t] = W;
}

// ============================================================
// Scalar chunk scan: prefix max over M, u-recurrence, alpha/gamma
// 1 block, 256 threads
// ============================================================
__global__ __launch_bounds__(256) void k_scan_scalar() {
    __shared__ float Pm[CC];
    __shared__ float al[CC], be[CC];
    __shared__ float us[CC];
    const int t = threadIdx.x;

    Pm[t] = g_M[t];
    Pm[t + 256] = g_M[t + 256];
    __syncthreads();

    // inclusive prefix max (Hillis-Steele), 2 elems/thread
    float c0 = Pm[t], c1 = Pm[t + 256];
    for (int off = 1; off < CC; off <<= 1) {
        float v0 = (t >= off) ? Pm[t - off] : NEG_INF;
        float v1 = (t + 256 >= off) ? Pm[t + 256 - off] : NEG_INF;
        __syncthreads();
        c0 = fmaxf(c0, v0); c1 = fmaxf(c1, v1);
        Pm[t] = c0; Pm[t + 256] = c1;
        __syncthreads();
    }

#pragma unroll
    for (int r = 0; r < 2; r++) {
        int i = t + r * 256;
        float Minc = Pm[i];
        float Mp = (i == 0) ? NEG_INF : Pm[i - 1];
        float a = (i == 0) ? 0.f : __expf(Mp - Minc);
        float g = __expf(g_M[i] - Minc);
        al[i] = a;
        be[i] = g_U[i] * g;
        g_Mp[i] = Mp;
        g_alpha[i] = a;
        g_gamma[i] = g;
    }
    __syncthreads();

    if (t == 0) {
        float u = 0.f;
#pragma unroll 8
        for (int cix = 0; cix < CC; cix++) {
            us[cix] = u;                 // exclusive, referenced to Mp_c
            u = u * al[cix] + be[cix];
        }
    }
    __syncthreads();
    g_Up[t] = us[t];
    g_Up[t + 256] = us[t + 256];
}

// ============================================================
// Segment-local W prefix scan: 8 blocks x 64 chunks, register-resident
// ============================================================
__global__ __launch_bounds__(256) void k_segscan() {
    __shared__ float al[64], ga[64];
    const int b = blockIdx.x;
    const int t = threadIdx.x;
    if (t < 64) {
        al[t] = g_alpha[b * 64 + t];
        ga[t] = g_gamma[b * 64 + t];
    }
    __syncthreads();

    const float* Wsrc = g_W + (size_t)b * 64 * DD + t;
    float* Wdst = g_Wp + (size_t)b * 64 * DD + t;

    float wc[64];
#pragma unroll
    for (int j = 0; j < 64; j++) wc[j] = Wsrc[(size_t)j * DD];

    float w = 0.f;
#pragma unroll
    for (int j = 0; j < 64; j++) {
        Wdst[(size_t)j * DD] = w;            // exclusive within segment, ref Mp_c
        w = w * al[j] + wc[j] * ga[j];
    }
    g_seg[b * DD + t] = w;                    // ref Minc[segment end]
}

// ============================================================
// Carry combine across 8 segments (1 block)
// ============================================================
__global__ __launch_bounds__(256) void k_carry() {
    const int t = threadIdx.x;
    float w = 0.f;
#pragma unroll
    for (int b = 0; b < NSEG; b++) {
        g_carry[b * DD + t] = w;              // ref Mp[64*b]
        if (b < NSEG - 1) {
            float sc = (b == 0) ? 0.f : __expf(g_Mp[b * 64] - g_Mp[(b + 1) * 64]);
            w = w * sc + g_seg[b * DD + t];
        }
    }
}

// ============================================================
// Pass 2: rebuild per-row recurrence, stream V -> out
// ============================================================
__global__ __launch_bounds__(256) void k_pass2(const float* __restrict__ V,
                                               float* __restrict__ out) {
    __shared__ float s_loc[RR], m_sh[RR];
    __shared__ float a_sh[RR], b_sh[RR];
    __shared__ float u_sh[RR], inv_sh[RR];

    const int c = blockIdx.x;
    const int t = threadIdx.x;

    const float Mp_c = g_Mp[c];
    const float Up_c = g_Up[c];

    if (t < RR) {
        float sv = g_s[c * RR + t];
        s_loc[t] = sv;
        m_sh[t] = sv;
    }
    __syncthreads();

    // inclusive prefix max over s within the chunk
#pragma unroll
    for (int off = 1; off < RR; off <<= 1) {
        float v = NEG_INF;
        if (t < RR && t >= off) v = m_sh[t - off];
        __syncthreads();
        if (t < RR) m_sh[t] = fmaxf(m_sh[t], v);
        __syncthreads();
    }

    if (t < RR) {
        float mi = fmaxf(m_sh[t], Mp_c);
        float mp = (t == 0) ? Mp_c : fmaxf(m_sh[t - 1], Mp_c);
        a_sh[t] = __expf(mp - mi);            // exp(-inf - finite) = 0 : safe
        b_sh[t] = __expf(s_loc[t] - mi);
    }
    __syncthreads();

    if (t == 0) {
        float u = Up_c;
#pragma unroll 8
        for (int i = 0; i < RR; i++) {
            u = u * a_sh[i] + b_sh[i];
            u_sh[i] = u;
        }
    }
    __syncthreads();
    if (t < RR) inv_sh[t] = 1.0f / u_sh[t];
    __syncthreads();

    // seed w[d] = Wp_c[d] + carry[seg][d] * exp(Mp_seg - Mp_c)
    const int seg = c >> 6;
    float w = g_Wp[(size_t)c * DD + t];
    if (seg > 0) {
        w += g_carry[seg * DD + t] * __expf(g_Mp[seg * 64] - Mp_c);
    }

    const float* Vb = V + (size_t)c * RR * DD + t;
    float* Ob = out + (size_t)c * RR * DD + t;

    float cur[8];
#pragma unroll
    for (int j = 0; j < 8; j++) cur[j] = Vb[(size_t)j * DD];

    for (int ib = 0; ib < RR; ib += 8) {
        float nxt[8];
#pragma unroll
        for (int j = 0; j < 8; j++)
            nxt[j] = (ib + 8 < RR) ? Vb[(size_t)(ib + 8 + j) * DD] : 0.f;
#pragma unroll
        for (int j = 0; j < 8; j++) {
            int i = ib + j;
            w = w * a_sh[i] + b_sh[i] * cur[j];
            Ob[(size_t)i * DD] = w * inv_sh[i];
        }
#pragma unroll
        for (int j = 0; j < 8; j++) cur[j] = nxt[j];
    }
}

// ============================================================
extern "C" void kernel_launch(void* const* d_in, const int* in_sizes, int n_in,
                              void* d_out, int out_size) {
    const float* K = (const float*)d_in[0];
    const float* V = (const float*)d_in[1];
    const float* q = (const float*)d_in[2];
    float* out = (float*)d_out;

    k_pass1<<<CC, 256>>>(K, V, q);
    k_scan_scalar<<<1, 256>>>();
    k_segscan<<<NSEG, 256>>>();
    k_carry<<<1, 256>>>();
    k_pass2<<<CC, 256>>>(V, out);
}